// round 14
// baseline (speedup 1.0000x reference)
#include <cuda_runtime.h>
#include <cuda_fp16.h>
#include <math.h>
#include <stdint.h>

// ---------------------------------------------------------------------------
// Problem constants (fixed instance)
// ---------------------------------------------------------------------------
constexpr int Bc  = 2;
constexpr int Cc  = 256;
constexpr int NHc = 8;
constexpr int Lc  = 4;
constexpr int Pc  = 4;
constexpr int LVc = 13294;       // 100*100 + 50*50 + 25*25 + 13*13
constexpr int LQc = 13294;
constexpr int Mrows = Bc * LQc;  // 26588
constexpr int PROJW = NHc * Lc * Pc * 2 + NHc * Lc * Pc; // 384

// Scratch (device globals; no allocation allowed)
__device__ __half g_val [Bc * LVc * Cc];    // [b][lv][c]  fp16
__device__ __half g_proj[Bc * LQc * PROJW]; // [b][q][384] fp16
__device__ __half g_msda[Bc * LQc * Cc];    // [b][q][c]   fp16

// ---------------------------------------------------------------------------
// fp16 MMA helpers
// ---------------------------------------------------------------------------
__device__ __forceinline__ uint32_t pack_h2(float a, float b) {
    __half2 h = __floats2half2_rn(a, b);
    return *reinterpret_cast<uint32_t*>(&h);
}
__device__ __forceinline__ void ldmatrix_x4(uint32_t (&r)[4], uint32_t saddr) {
    asm volatile("ldmatrix.sync.aligned.m8n8.x4.shared.b16 {%0,%1,%2,%3}, [%4];"
                 : "=r"(r[0]), "=r"(r[1]), "=r"(r[2]), "=r"(r[3])
                 : "r"(saddr));
}
__device__ __forceinline__ void mma_f16(float (&d)[4],
                                        const uint32_t (&a)[4],
                                        const uint32_t b0, const uint32_t b1) {
    asm volatile(
        "mma.sync.aligned.m16n8k16.row.col.f32.f16.f16.f32 "
        "{%0,%1,%2,%3}, {%4,%5,%6,%7}, {%8,%9}, {%0,%1,%2,%3};"
        : "+f"(d[0]), "+f"(d[1]), "+f"(d[2]), "+f"(d[3])
        : "r"(a[0]), "r"(a[1]), "r"(a[2]), "r"(a[3]), "r"(b0), "r"(b1));
}

// ---------------------------------------------------------------------------
// FUSED projection GEMMs: BM=128, BN=64, BK=32; 8 warps (4x2), warp tile
// 32x32 (2x4 m16n8k16). 2 blocks/SM (launch_bounds cap 128 regs).
// blockIdx.y dispatch (gm x 10):
//   y=0..3 : g_val[m][y*64..]      = value @ Wv[:, y*64..]  + bv     (ldc 256)
//   y=4..7 : g_proj[m][(y-4)*64..] = query @ Woff[:, ..]    + boff   (ldc 384)
//   y=8..9 : g_proj[m][256+(y-8)*64..] = query @ Wattn[:, ..] + battn
// A rows interleaved: m = b*13294 + s at A[(s*2+b)*256 + k]. fp16 out.
// ---------------------------------------------------------------------------
__global__ __launch_bounds__(256, 2)
void hgemm_proj_fused(const float* __restrict__ value,
                      const float* __restrict__ query,
                      const float* __restrict__ Wv,   const float* __restrict__ bv,
                      const float* __restrict__ Woff, const float* __restrict__ boff,
                      const float* __restrict__ Wattn,const float* __restrict__ battn,
                      __half* __restrict__ valp, __half* __restrict__ projp)
{
    __shared__ __half    As[2][128][40];    // [stage][m][k-half]
    __shared__ uint32_t  Bp[2][16][72];     // [stage][kpair][n] packed half2

    const int tid  = threadIdx.x;
    const int warp = tid >> 5;
    const int lane = tid & 31;
    const int wm = warp >> 1;          // 0..3 : 32-row slab
    const int wn = warp & 1;           // 0..1 : 32-col slab
    const int m0 = blockIdx.x * 128;
    const int gy = blockIdx.y;
    const int qr = lane >> 2;          // 0..7
    const int qc = lane & 3;           // 0..3

    // ---- dispatch ----
    const float* A;  const float* W;  const float* bias;
    __half* Cout;  int ldw, ldc, outc0;
    if (gy < 4) {
        A = value; W = Wv + gy * 64;   bias = bv + gy * 64;
        Cout = valp;  ldw = 256; ldc = 256; outc0 = gy * 64;
    } else if (gy < 8) {
        A = query; W = Woff + (gy - 4) * 64; bias = boff + (gy - 4) * 64;
        Cout = projp; ldw = 256; ldc = PROJW; outc0 = (gy - 4) * 64;
    } else {
        A = query; W = Wattn + (gy - 8) * 64; bias = battn + (gy - 8) * 64;
        Cout = projp; ldw = 128; ldc = PROJW; outc0 = 256 + (gy - 8) * 64;
    }

    // ---- staging slots ----
    // A: 512 dual-float4 slots (128 rows x 4 col-octets), 2 per thread
    int arow[2], ac8[2];
    const float* aptr[2];
    #pragma unroll
    for (int r = 0; r < 2; r++) {
        int idx = tid + r * 256;
        arow[r] = idx >> 2;
        ac8[r]  = (idx & 3) * 8;
        int m = m0 + arow[r];
        if (m < Mrows) {
            int b = m / LQc; int s = m - b * LQc;
            aptr[r] = A + (s * Bc + b) * Cc;
        } else aptr[r] = nullptr;
    }
    // B: 256 slots (16 kpairs x 16 n-quads), 1 per thread
    const int wkp = tid >> 4;          // 0..15
    const int wn4 = (tid & 15) * 4;    // 0..60

    float acc[2][4][4];
    #pragma unroll
    for (int mt = 0; mt < 2; mt++)
        #pragma unroll
        for (int nt = 0; nt < 4; nt++)
            #pragma unroll
            for (int c = 0; c < 4; c++) acc[mt][nt][c] = 0.f;

    const float4 f4z = make_float4(0.f, 0.f, 0.f, 0.f);

    float4 na[2][2], nw[2];
    auto load_tile = [&](int kb) {
        #pragma unroll
        for (int r = 0; r < 2; r++) {
            if (aptr[r]) {
                na[r][0] = *(const float4*)(aptr[r] + kb + ac8[r]);
                na[r][1] = *(const float4*)(aptr[r] + kb + ac8[r] + 4);
            } else { na[r][0] = f4z; na[r][1] = f4z; }
        }
        nw[0] = *(const float4*)(W + (kb + 2 * wkp    ) * ldw + wn4);
        nw[1] = *(const float4*)(W + (kb + 2 * wkp + 1) * ldw + wn4);
    };
    auto store_tile = [&](int st) {
        #pragma unroll
        for (int r = 0; r < 2; r++) {
            uint4 a4;
            a4.x = pack_h2(na[r][0].x, na[r][0].y);
            a4.y = pack_h2(na[r][0].z, na[r][0].w);
            a4.z = pack_h2(na[r][1].x, na[r][1].y);
            a4.w = pack_h2(na[r][1].z, na[r][1].w);
            *(uint4*)&As[st][arow[r]][ac8[r]] = a4;
        }
        uint4 w4;
        w4.x = pack_h2(nw[0].x, nw[1].x);
        w4.y = pack_h2(nw[0].y, nw[1].y);
        w4.z = pack_h2(nw[0].z, nw[1].z);
        w4.w = pack_h2(nw[0].w, nw[1].w);
        *(uint4*)&Bp[st][wkp][wn4] = w4;
    };

    load_tile(0);
    store_tile(0);
    __syncthreads();

    #pragma unroll 1
    for (int kk = 0; kk < Cc / 32; kk++) {
        const int cur = kk & 1;
        if (kk < Cc / 32 - 1) load_tile((kk + 1) * 32);

        #pragma unroll
        for (int ks = 0; ks < 32; ks += 16) {
            uint32_t afr[2][4];
            #pragma unroll
            for (int mt = 0; mt < 2; mt++) {
                int rowb = wm * 32 + mt * 16;
                int row = rowb + (lane & 7) + ((lane >> 3) & 1) * 8;
                int col = ks + (lane >> 4) * 8;
                uint32_t sa = (uint32_t)__cvta_generic_to_shared(&As[cur][row][col]);
                ldmatrix_x4(afr[mt], sa);
            }
            uint32_t bfr[4][2];
            #pragma unroll
            for (int nt = 0; nt < 4; nt++) {
                int col = wn * 32 + nt * 8 + qr;
                bfr[nt][0] = Bp[cur][ks / 2 + qc    ][col];
                bfr[nt][1] = Bp[cur][ks / 2 + qc + 4][col];
            }
            #pragma unroll
            for (int mt = 0; mt < 2; mt++)
                #pragma unroll
                for (int nt = 0; nt < 4; nt++)
                    mma_f16(acc[mt][nt], afr[mt], bfr[nt][0], bfr[nt][1]);
        }

        if (kk < Cc / 32 - 1) {
            store_tile(cur ^ 1);
            __syncthreads();
        }
    }

    // ---- epilogue: fp16 output ----
    float2 bvals[4];
    #pragma unroll
    for (int nt = 0; nt < 4; nt++) {
        bvals[nt] = *(const float2*)&bias[wn * 32 + nt * 8 + qc * 2];
    }

    #pragma unroll
    for (int mt = 0; mt < 2; mt++) {
        #pragma unroll
        for (int hrow = 0; hrow < 2; hrow++) {
            int m = m0 + wm * 32 + mt * 16 + qr + hrow * 8;
            if (m >= Mrows) continue;
            int obase = m * ldc + outc0;
            #pragma unroll
            for (int nt = 0; nt < 4; nt++) {
                int col = wn * 32 + nt * 8 + qc * 2;
                float vx = acc[mt][nt][hrow * 2 + 0] + bvals[nt].x;
                float vy = acc[mt][nt][hrow * 2 + 1] + bvals[nt].y;
                __half2* op = (__half2*)(Cout + obase + col);
                *op = __floats2half2_rn(vx, vy);
            }
        }
    }
}

// ---------------------------------------------------------------------------
// Output-projection GEMM: out = g_msda(fp16) @ Wo + bo + query (residual),
// output interleaved (s*2+b)*256. BM=128, BN=64, BK=32, warp tile 32x32.
// ---------------------------------------------------------------------------
__global__ __launch_bounds__(256, 2)
void hgemm_out(const __half* __restrict__ Ain, const float* __restrict__ W,
               const float* __restrict__ bias, float* __restrict__ Cout,
               const float* __restrict__ resid)
{
    __shared__ __half    As[2][128][40];
    __shared__ uint32_t  Bp[2][16][72];

    const int tid  = threadIdx.x;
    const int warp = tid >> 5;
    const int lane = tid & 31;
    const int wm = warp >> 1;
    const int wn = warp & 1;
    const int m0 = blockIdx.x * 128;
    const int n0 = blockIdx.y * 64;
    const int qr = lane >> 2;
    const int qc = lane & 3;

    int arow[2], ac8[2];
    const __half* aptr[2];
    #pragma unroll
    for (int r = 0; r < 2; r++) {
        int idx = tid + r * 256;
        arow[r] = idx >> 2;
        ac8[r]  = (idx & 3) * 8;
        int m = m0 + arow[r];
        aptr[r] = (m < Mrows) ? Ain + m * Cc : nullptr;
    }
    const int wkp = tid >> 4;
    const int wn4 = (tid & 15) * 4;
    const float* wbase = W + n0;

    float acc[2][4][4];
    #pragma unroll
    for (int mt = 0; mt < 2; mt++)
        #pragma unroll
        for (int nt = 0; nt < 4; nt++)
            #pragma unroll
            for (int c = 0; c < 4; c++) acc[mt][nt][c] = 0.f;

    uint4 ua[2];
    float4 nw[2];
    auto load_tile = [&](int kb) {
        #pragma unroll
        for (int r = 0; r < 2; r++) {
            ua[r] = aptr[r] ? *(const uint4*)(aptr[r] + kb + ac8[r])
                            : make_uint4(0, 0, 0, 0);
        }
        nw[0] = *(const float4*)(wbase + (kb + 2 * wkp    ) * Cc + wn4);
        nw[1] = *(const float4*)(wbase + (kb + 2 * wkp + 1) * Cc + wn4);
    };
    auto store_tile = [&](int st) {
        #pragma unroll
        for (int r = 0; r < 2; r++) {
            *(uint4*)&As[st][arow[r]][ac8[r]] = ua[r];
        }
        uint4 w4;
        w4.x = pack_h2(nw[0].x, nw[1].x);
        w4.y = pack_h2(nw[0].y, nw[1].y);
        w4.z = pack_h2(nw[0].z, nw[1].z);
        w4.w = pack_h2(nw[0].w, nw[1].w);
        *(uint4*)&Bp[st][wkp][wn4] = w4;
    };

    load_tile(0);
    store_tile(0);
    __syncthreads();

    #pragma unroll 1
    for (int kk = 0; kk < Cc / 32; kk++) {
        const int cur = kk & 1;
        if (kk < Cc / 32 - 1) load_tile((kk + 1) * 32);

        #pragma unroll
        for (int ks = 0; ks < 32; ks += 16) {
            uint32_t afr[2][4];
            #pragma unroll
            for (int mt = 0; mt < 2; mt++) {
                int rowb = wm * 32 + mt * 16;
                int row = rowb + (lane & 7) + ((lane >> 3) & 1) * 8;
                int col = ks + (lane >> 4) * 8;
                uint32_t sa = (uint32_t)__cvta_generic_to_shared(&As[cur][row][col]);
                ldmatrix_x4(afr[mt], sa);
            }
            uint32_t bfr[4][2];
            #pragma unroll
            for (int nt = 0; nt < 4; nt++) {
                int col = wn * 32 + nt * 8 + qr;
                bfr[nt][0] = Bp[cur][ks / 2 + qc    ][col];
                bfr[nt][1] = Bp[cur][ks / 2 + qc + 4][col];
            }
            #pragma unroll
            for (int mt = 0; mt < 2; mt++)
                #pragma unroll
                for (int nt = 0; nt < 4; nt++)
                    mma_f16(acc[mt][nt], afr[mt], bfr[nt][0], bfr[nt][1]);
        }

        if (kk < Cc / 32 - 1) {
            store_tile(cur ^ 1);
            __syncthreads();
        }
    }

    float2 bvals[4];
    #pragma unroll
    for (int nt = 0; nt < 4; nt++) {
        bvals[nt] = *(const float2*)&bias[n0 + wn * 32 + nt * 8 + qc * 2];
    }

    #pragma unroll
    for (int mt = 0; mt < 2; mt++) {
        #pragma unroll
        for (int hrow = 0; hrow < 2; hrow++) {
            int m = m0 + wm * 32 + mt * 16 + qr + hrow * 8;
            if (m >= Mrows) continue;
            int b = m / LQc; int s = m - b * LQc;
            int obase = (s * Bc + b) * Cc;
            #pragma unroll
            for (int nt = 0; nt < 4; nt++) {
                int n = n0 + wn * 32 + nt * 8 + qc * 2;
                float vx = acc[mt][nt][hrow * 2 + 0] + bvals[nt].x;
                float vy = acc[mt][nt][hrow * 2 + 1] + bvals[nt].y;
                float2 rr = *(const float2*)&resid[obase + n];
                vx += rr.x; vy += rr.y;
                *(float2*)&Cout[obase + n] = make_float2(vx, vy);
            }
        }
    }
}

// ---------------------------------------------------------------------------
// Fused softmax + bilinear sampling — 2 queries/warp, 4 points in parallel,
// 8 channels per lane (LDG.128), per-level HFMA2 corner accumulation.
// (R11-best configuration, channel-major g_val.)
// ---------------------------------------------------------------------------
#define SHFL16(v, s) __shfl_sync(0xffffffffu, (v), (s), 16)

__device__ __forceinline__ void corner_acc_h2(__half2 (&hacc)[4], const uint4* p,
                                              __half2 w) {
    uint4 u = *p;
    hacc[0] = __hfma2(*reinterpret_cast<__half2*>(&u.x), w, hacc[0]);
    hacc[1] = __hfma2(*reinterpret_cast<__half2*>(&u.y), w, hacc[1]);
    hacc[2] = __hfma2(*reinterpret_cast<__half2*>(&u.z), w, hacc[2]);
    hacc[3] = __hfma2(*reinterpret_cast<__half2*>(&u.w), w, hacc[3]);
}

__global__ __launch_bounds__(512, 3)
void msda_sample(const float* __restrict__ rp,
                 const __half* __restrict__ val,
                 const __half* __restrict__ proj,
                 __half* __restrict__ msda)
{
    const int gw   = (blockIdx.x * 512 + threadIdx.x) >> 5;
    const int lane = threadIdx.x & 31;
    const int pair = gw >> 3;
    const int h    = gw & 7;
    const int hl   = lane & 15;            // lane within query-half
    const int bq   = pair * 2 + (lane >> 4);
    const int g4   = hl >> 2;              // 0..3 point group
    const int cq   = hl & 3;               // channel octet (8 ch)
    const int b    = bq / LQc;

    const __half* prow = proj + bq * PROJW;
    float off0 = __half2float(prow[h * 32 + hl]);        // offsets 0..15
    float off1 = __half2float(prow[h * 32 + 16 + hl]);   // offsets 16..31
    float lg   = __half2float(prow[256 + h * 16 + hl]);  // 16 logits
    float rpv  = 0.f;
    if (hl < 8) {
        rpv = rp[bq * (Lc * 2) + hl];
        rpv = fminf(fmaxf(rpv, 1e-5f), 1.f - 1e-5f);
    }

    // Softmax over 16 logits (xor 1..8 stays within each 16-lane half)
    float mx = lg;
    #pragma unroll
    for (int o = 8; o > 0; o >>= 1)
        mx = fmaxf(mx, __shfl_xor_sync(0xffffffffu, mx, o));
    float e = __expf(lg - mx);
    float sum = e;
    #pragma unroll
    for (int o = 8; o > 0; o >>= 1)
        sum += __shfl_xor_sync(0xffffffffu, sum, o);
    float attn_val = e / sum;

    constexpr int HH[4] = {100, 50, 25, 13};
    constexpr int ST[4] = {0, 10000, 12500, 13125};

    // uint4 units: 256 halves/pixel = 32 uint4; lane covers 8 channels
    const uint4* vb = (const uint4*)val + (b * LVc) * 32 + h * 4 + cq;

    float acc[8];
    #pragma unroll
    for (int j = 0; j < 8; j++) acc[j] = 0.f;

    #pragma unroll
    for (int l = 0; l < Lc; l++) {
        const int   Wl = HH[l];
        const int   st = ST[l];
        const float fW = (float)HH[l];

        float rpx = SHFL16(rpv, 2 * l);
        float rpy = SHFL16(rpv, 2 * l + 1);

        const int oidx = l * 8 + 2 * g4;   // offset-pair index for this point
        float offx, offy;
        if (l < 2) { offx = SHFL16(off0, oidx);      offy = SHFL16(off0, oidx + 1); }
        else       { offx = SHFL16(off1, oidx - 16); offy = SHFL16(off1, oidx - 15); }
        float a = SHFL16(attn_val, l * 4 + g4);

        float x = fmaf(rpx, fW, offx) - 0.5f;
        float y = fmaf(rpy, fW, offy) - 0.5f;
        float x0f = floorf(x), y0f = floorf(y);
        int x0 = (int)x0f, y0 = (int)y0f;
        float wx = x - x0f, wy = y - y0f;

        float w00 = a * (1.f - wy) * (1.f - wx);
        float w01 = a * (1.f - wy) * wx;
        float w10 = a * wy * (1.f - wx);
        float w11 = a * wy * wx;

        int x1 = x0 + 1, y1 = y0 + 1;
        bool vx0 = (x0 >= 0) & (x0 < Wl);
        bool vx1 = (x1 >= 0) & (x1 < Wl);
        bool vy0 = (y0 >= 0) & (y0 < Wl);
        bool vy1 = (y1 >= 0) & (y1 < Wl);

        int row0 = (st + y0 * Wl) * 32;
        int row1 = row0 + Wl * 32;

        // Per-level fp16 corner accumulation (4 HFMA2 per corner)
        __half2 hz = __float2half2_rn(0.f);
        __half2 hacc[4] = {hz, hz, hz, hz};
        if (vy0 & vx0) corner_acc_h2(hacc, vb + row0 + x0 * 32, __float2half2_rn(w00));
        if (vy0 & vx1) corner_acc_h2(hacc, vb + row0 + x1 * 32, __float2half2_rn(w01));
        if (vy1 & vx0) corner_acc_h2(hacc, vb + row1 + x0 * 32, __float2half2_rn(w10));
        if (vy1 & vx1) corner_acc_h2(hacc, vb + row1 + x1 * 32, __float2half2_rn(w11));

        // Fold level partial into fp32 master accumulator
        #pragma unroll
        for (int j = 0; j < 4; j++) {
            float2 t = __half22float2(hacc[j]);
            acc[2 * j]     += t.x;
            acc[2 * j + 1] += t.y;
        }
    }

    // Reduce across the 4 point-groups (hl bits 2,3 -> xor 4, xor 8)
    #pragma unroll
    for (int j = 0; j < 8; j++) {
        acc[j] += __shfl_xor_sync(0xffffffffu, acc[j], 4);
        acc[j] += __shfl_xor_sync(0xffffffffu, acc[j], 8);
    }

    if (g4 == 0) {
        uint4 o;
        o.x = pack_h2(acc[0], acc[1]);
        o.y = pack_h2(acc[2], acc[3]);
        o.z = pack_h2(acc[4], acc[5]);
        o.w = pack_h2(acc[6], acc[7]);
        ((uint4*)msda)[bq * 32 + h * 4 + cq] = o;
    }
}

// ---------------------------------------------------------------------------
extern "C" void kernel_launch(void* const* d_in, const int* in_sizes, int n_in,
                              void* d_out, int out_size)
{
    const float* query = (const float*)d_in[0];   // (LQ, B, C)
    const float* rp    = (const float*)d_in[1];   // (B, LQ, L, 2)
    const float* value = (const float*)d_in[2];   // (LV, B, C)
    const float* Wv    = (const float*)d_in[5];
    const float* bv    = (const float*)d_in[6];
    const float* Woff  = (const float*)d_in[7];
    const float* boff  = (const float*)d_in[8];
    const float* Wattn = (const float*)d_in[9];
    const float* battn = (const float*)d_in[10];
    const float* Wo    = (const float*)d_in[11];
    const float* bo    = (const float*)d_in[12];
    float* out = (float*)d_out;

    __half *valp, *msdap, *projp;
    cudaGetSymbolAddress((void**)&valp,  g_val);
    cudaGetSymbolAddress((void**)&projp, g_proj);
    cudaGetSymbolAddress((void**)&msdap, g_msda);

    const int gm = (Mrows + 127) / 128;   // 208

    // 1) all projections in ONE launch (2080 blocks): g_val + g_proj
    hgemm_proj_fused<<<dim3(gm, 10), 256>>>(value, query, Wv, bv,
                                            Woff, boff, Wattn, battn,
                                            valp, projp);
    // 2) softmax + bilinear sampling -> fp16 g_msda
    msda_sample<<<(Mrows / 2 * NHc) / 16, 512>>>(rp, valp, projp, msdap);
    // 3) output projection + bias + residual -> d_out
    hgemm_out<<<dim3(gm, 4), 256>>>(msdap, Wo, bo, out, query);
}